// round 1
// baseline (speedup 1.0000x reference)
#include <cuda_runtime.h>

#define D 8
#define NTOT 1024

// ---- constant table layout (filled by precompute kernel from lengthscale/sigma) ----
#define OFF_INV2 0      // inv2[a][k] = 1/L[a,k]^2              (64)
#define OFF_A    64     // A[c][j] = sigma[j]/lij2[j]^2 * M^2   (64)
#define OFF_B    128    // B[c][j] = 1/M[c,j]                   (64)
#define OFF_LIJ2 192    // lij2[j] = L[0,j]^2                   (8)
#define OFF_C1   200    // 5*tl + lij2*tl^2                     (8)
#define OFF_C2   208    // tl^2                                 (8)
#define OFF_C3   216    // 2 + lij2*tl                          (8)
#define OFF_COEF 224    // sigma[d]/lij2[d]^2                   (8)
#define OFF_SIG0 232    // sigma[0]                             (1)
#define TAB_SIZE 233

__device__ float g_tab[TAB_SIZE];

__global__ void precompute_kernel(const float* __restrict__ L,
                                  const float* __restrict__ sigma) {
    if (threadIdx.x != 0 || blockIdx.x != 0) return;
    float inv2[D][D];
    for (int j = 0; j < D; j++)
        for (int k = 0; k < D; k++) {
            float l = L[j * D + k];
            inv2[j][k] = 1.0f / (l * l);
            g_tab[OFF_INV2 + j * D + k] = inv2[j][k];
        }
    float lij2[D];
    for (int j = 0; j < D; j++) {
        float l0 = L[0 * D + j];
        lij2[j] = l0 * l0;
        g_tab[OFF_LIJ2 + j] = lij2[j];
    }
    for (int c = 0; c < D; c++)
        for (int j = 0; j < D; j++) {
            float M = inv2[0][c] + inv2[j][c];
            g_tab[OFF_A + c * D + j] = sigma[j] / (lij2[j] * lij2[j]) * M * M;
            g_tab[OFF_B + c * D + j] = 1.0f / M;
        }
    for (int d = 0; d < D; d++) {
        float tl = inv2[0][d] + inv2[d][d];
        g_tab[OFF_C1 + d] = 5.0f * tl + lij2[d] * tl * tl;
        g_tab[OFF_C2 + d] = tl * tl;
        g_tab[OFF_C3 + d] = 2.0f + lij2[d] * tl;
        g_tab[OFF_COEF + d] = sigma[d] / (lij2[d] * lij2[d]);
    }
    g_tab[OFF_SIG0] = sigma[0];
}

// ---- main kernel: each thread computes MI outputs (same n, MI m's 32 apart) ----
#define BX 32
#define BY 4
#define MI 4
// block tile: (BX*MI)=128 m  x  BY=4 n, 128 threads

__global__ __launch_bounds__(BX * BY)
void taylor_rbf_kernel(const float* __restrict__ x1,
                       const float* __restrict__ x2,
                       float* __restrict__ out) {
    __shared__ float sh[TAB_SIZE];
    __shared__ float shx2[D][BX * MI];   // [k][m_local], conflict-free reads

    const int tid = threadIdx.y * BX + threadIdx.x;
    const int nthreads = BX * BY;
    for (int i = tid; i < TAB_SIZE; i += nthreads) sh[i] = g_tab[i];

    const int m0 = blockIdx.x * (BX * MI);
    for (int i = tid; i < BX * MI * D; i += nthreads) {
        int ml = i / D, k = i % D;               // contiguous global read
        shx2[k][ml] = x2[(m0 + ml) * D + k];
    }
    __syncthreads();

    const int n = blockIdx.y * BY + threadIdx.y;
    float a1[D];
#pragma unroll
    for (int k = 0; k < D; k++) a1[k] = x1[n * D + k];

    // diff2[mi][k] = (x1[n,k] - x2[m,k])^2
    float diff2[MI][D];
#pragma unroll
    for (int mi = 0; mi < MI; mi++) {
        int ml = threadIdx.x + mi * BX;
#pragma unroll
        for (int k = 0; k < D; k++) {
            float dd = a1[k] - shx2[k][ml];
            diff2[mi][k] = dd * dd;
        }
    }

    // e[mi][a] = exp(-0.5 * <diff2, inv2[a,:]>);  e[mi][0] is the shared e0 factor
    float e[MI][D];
#pragma unroll
    for (int a = 0; a < D; a++) {
        float row[D];
#pragma unroll
        for (int k = 0; k < D; k++) row[k] = sh[OFF_INV2 + a * D + k];
#pragma unroll
        for (int mi = 0; mi < MI; mi++) {
            float s = 0.0f;
#pragma unroll
            for (int k = 0; k < D; k++) s = fmaf(diff2[mi][k], row[k], s);
            e[mi][a] = __expf(-0.5f * s);
        }
    }

    float total[MI];
#pragma unroll
    for (int mi = 0; mi < MI; mi++) total[mi] = 0.0f;

    // double sum over (c, j) of outer[c,j]/e0
#pragma unroll
    for (int j = 0; j < D; j++) {
        float lj = sh[OFF_LIJ2 + j];
        float inner[MI];
#pragma unroll
        for (int mi = 0; mi < MI; mi++) inner[mi] = 0.0f;
#pragma unroll
        for (int c = 0; c < D; c++) {
            float Acj = sh[OFF_A + c * D + j];
            float Bcj = sh[OFF_B + c * D + j];
#pragma unroll
            for (int mi = 0; mi < MI; mi++)
                inner[mi] = fmaf(Acj * (Bcj - diff2[mi][c]), e[mi][c], inner[mi]);
        }
#pragma unroll
        for (int mi = 0; mi < MI; mi++)
            total[mi] = fmaf(inner[mi] * (lj - diff2[mi][j]), e[mi][j], total[mi]);
    }

    // diagonal correction: + (desired - current_diag) per d, both carry e0*e_d^2
#pragma unroll
    for (int d = 0; d < D; d++) {
        float Add = sh[OFF_A + d * D + d];
        float Bdd = sh[OFF_B + d * D + d];
        float ld  = sh[OFF_LIJ2 + d];
        float c1  = sh[OFF_C1 + d];
        float c2  = sh[OFF_C2 + d];
        float c3  = sh[OFF_C3 + d];
        float cf  = sh[OFF_COEF + d];
#pragma unroll
        for (int mi = 0; mi < MI; mi++) {
            float dd  = diff2[mi][d];
            float ed2 = e[mi][d] * e[mi][d];
            float cur = Add * (Bdd - dd) * (ld - dd);
            float poly = fmaf(dd, fmaf(c2, dd, -c1), c3);
            total[mi] = fmaf(fmaf(cf, poly, -cur), ed2, total[mi]);
        }
    }

    const float s0 = sh[OFF_SIG0];
#pragma unroll
    for (int mi = 0; mi < MI; mi++) {
        int m = m0 + threadIdx.x + mi * BX;
        out[n * NTOT + m] = s0 * e[mi][0] * total[mi];
    }
}

extern "C" void kernel_launch(void* const* d_in, const int* in_sizes, int n_in,
                              void* d_out, int out_size) {
    const float* x1    = (const float*)d_in[0];
    const float* x2    = (const float*)d_in[1];
    const float* L     = (const float*)d_in[2];
    const float* sigma = (const float*)d_in[3];
    float* out = (float*)d_out;

    precompute_kernel<<<1, 32>>>(L, sigma);

    dim3 block(BX, BY);
    dim3 grid(NTOT / (BX * MI), NTOT / BY);   // (8, 256)
    taylor_rbf_kernel<<<grid, block>>>(x1, x2, out);
}

// round 2
// speedup vs baseline: 1.6465x; 1.6465x over previous
#include <cuda_runtime.h>

#define D 8
#define NTOT 1024
#define BX 32
#define BY 4
#define NPAIR 2   // MI=4 outputs per thread as 2 f32x2 pairs

typedef unsigned long long u64;

__device__ __forceinline__ u64 pack2(float lo, float hi) {
    u64 r; asm("mov.b64 %0, {%1,%2};" : "=l"(r) : "f"(lo), "f"(hi)); return r;
}
__device__ __forceinline__ void unpack2(u64 v, float& lo, float& hi) {
    asm("mov.b64 {%0,%1}, %2;" : "=f"(lo), "=f"(hi) : "l"(v));
}
__device__ __forceinline__ u64 fma2(u64 a, u64 b, u64 c) {
    u64 d; asm("fma.rn.f32x2 %0, %1, %2, %3;" : "=l"(d) : "l"(a), "l"(b), "l"(c)); return d;
}
__device__ __forceinline__ u64 mul2(u64 a, u64 b) {
    u64 d; asm("mul.rn.f32x2 %0, %1, %2;" : "=l"(d) : "l"(a), "l"(b)); return d;
}
__device__ __forceinline__ float ex2f(float x) {
    float r; asm("ex2.approx.ftz.f32 %0, %1;" : "=f"(r) : "f"(x)); return r;
}

// Shared-table layout: every scalar constant stored as a duplicated float2 so
// one LDS.64 produces a broadcast f32x2 operand.
__global__ __launch_bounds__(BX * BY, 4)
void taylor_rbf_fused(const float* __restrict__ x1,
                      const float* __restrict__ x2,
                      const float* __restrict__ L,
                      const float* __restrict__ sigma,
                      float* __restrict__ out) {
    __shared__ float2 sAB[64];    // [c*8+j]  AB = sigma_j/lij2_j^2 * M          (positive)
    __shared__ float2 sAn[64];    // [c*8+j]  -A = -sigma_j/lij2_j^2 * M^2       (negated)
    __shared__ float2 sI[64];     // [a*8+k]  inv2[a][k] * (-0.5*log2(e))        (exp-ready)
    __shared__ float2 sLJ[D];     // lij2_j
    __shared__ float2 sC1n[D];    // -(5*tl + lij2*tl^2)
    __shared__ float2 sC2[D];     // tl^2
    __shared__ float2 sC3[D];     // 2 + lij2*tl
    __shared__ float2 sCF[D];     // sigma_d / lij2_d^2
    __shared__ float2 sAddn[D];   // -A[d][d]
    __shared__ float2 sBdd[D];    // B[d][d] = 1/tl
    __shared__ float  sSig0;
    __shared__ float2 sx2[D][NPAIR][BX];  // [k][pair][tx] = (x2[m], x2[m+32])

    const int tx = threadIdx.x, ty = threadIdx.y;
    const int tid = ty * BX + tx;

    // ---- per-block precompute of the constant table ----
    if (tid < 64) {
        const int c = tid >> 3, j = tid & 7;
        float Ljc = L[j * D + c];
        float L0c = L[c];                       // L[0][c]
        float i0c = 1.0f / (L0c * L0c);
        float ijc = 1.0f / (Ljc * Ljc);
        float M   = i0c + ijc;
        float l0j = L[j];                       // L[0][j]
        float lij2 = l0j * l0j;
        float cf  = sigma[j] / (lij2 * lij2);
        float A   = cf * M * M;
        float AB  = cf * M;                     // A * (1/M)
        sAB[tid] = make_float2(AB, AB);
        sAn[tid] = make_float2(-A, -A);
        // exp-ready scaled inv2, reusing tid as (a,k)
        const int a = tid >> 3, k = tid & 7;
        float Lak = L[a * D + k];
        float v = -0.72134752044448170368f / (Lak * Lak);   // -0.5*log2(e)/L^2
        sI[tid] = make_float2(v, v);
    }
    if (tid < D) {
        const int d = tid;
        float l0 = L[d];                        // L[0][d]
        float lij2 = l0 * l0;
        float Ldd = L[d * D + d];
        float i_dd = 1.0f / (Ldd * Ldd);
        float i0d  = 1.0f / (l0 * l0);
        float tl = i0d + i_dd;                  // == M[d][d]
        float cf = sigma[d] / (lij2 * lij2);
        float Add = cf * tl * tl;
        sLJ[d]   = make_float2(lij2, lij2);
        float c1 = 5.0f * tl + lij2 * tl * tl;
        sC1n[d]  = make_float2(-c1, -c1);
        sC2[d]   = make_float2(tl * tl, tl * tl);
        float c3 = 2.0f + lij2 * tl;
        sC3[d]   = make_float2(c3, c3);
        sCF[d]   = make_float2(cf, cf);
        sAddn[d] = make_float2(-Add, -Add);
        float bdd = 1.0f / tl;
        sBdd[d]  = make_float2(bdd, bdd);
    }
    if (tid == 0) sSig0 = sigma[0];

    // ---- stage x2 tile: pair m and m+32 into one float2 ----
    const int m0 = blockIdx.x * (BX * 2 * NPAIR);   // 128 m per block
    {
        const int r = tid;                 // local row 0..127
        const int p = r >> 6;              // pair index
        const int half = (r >> 5) & 1;     // 0 -> .x, 1 -> .y
        const int t = r & 31;
        const float* src = x2 + (m0 + r) * D;
        #pragma unroll
        for (int k = 0; k < D; k++) {
            float* dst = (float*)&sx2[k][p][t] + half;
            *dst = src[k];
        }
    }
    __syncthreads();

    const int n = blockIdx.y * BY + ty;
    const u64 NEG1 = pack2(-1.0f, -1.0f);

    // diff^2, packed over the m-pair
    u64 d2[NPAIR][D];
    #pragma unroll
    for (int k = 0; k < D; k++) {
        float v = x1[n * D + k];
        u64 a1 = pack2(v, v);
        #pragma unroll
        for (int p = 0; p < NPAIR; p++) {
            u64 xp = *(const u64*)&sx2[k][p][tx];
            u64 dd = fma2(xp, NEG1, a1);       // a1 - x2 (exact, single rounding)
            d2[p][k] = mul2(dd, dd);
        }
    }

    // e[p][a] = exp(-0.5 * <d2, inv2[a,:]>)  via pre-scaled rows + ex2
    u64 e[NPAIR][D];
    #pragma unroll
    for (int a = 0; a < D; a++) {
        u64 row[D];
        #pragma unroll
        for (int k = 0; k < D; k++) row[k] = *(const u64*)&sI[a * D + k];
        #pragma unroll
        for (int p = 0; p < NPAIR; p++) {
            u64 s = mul2(d2[p][0], row[0]);
            #pragma unroll
            for (int k = 1; k < D; k++) s = fma2(d2[p][k], row[k], s);
            float lo, hi; unpack2(s, lo, hi);
            e[p][a] = pack2(ex2f(lo), ex2f(hi));
        }
    }

    u64 tot[NPAIR];
    #pragma unroll
    for (int p = 0; p < NPAIR; p++) tot[p] = pack2(0.0f, 0.0f);

    // double sum over (c, j):  sum_j e_j*(lj - d2_j) * sum_c (AB - A*d2_c)*e_c
    #pragma unroll
    for (int j = 0; j < D; j++) {
        u64 inner[NPAIR];
        #pragma unroll
        for (int p = 0; p < NPAIR; p++) inner[p] = pack2(0.0f, 0.0f);
        #pragma unroll
        for (int c = 0; c < D; c++) {
            u64 ABp = *(const u64*)&sAB[c * D + j];
            u64 Anp = *(const u64*)&sAn[c * D + j];
            #pragma unroll
            for (int p = 0; p < NPAIR; p++) {
                u64 t = fma2(Anp, d2[p][c], ABp);          // AB - A*d2
                inner[p] = fma2(t, e[p][c], inner[p]);
            }
        }
        u64 ljp = *(const u64*)&sLJ[j];
        #pragma unroll
        for (int p = 0; p < NPAIR; p++) {
            u64 w = fma2(d2[p][j], NEG1, ljp);             // lj - d2_j
            tot[p] = fma2(mul2(inner[p], w), e[p][j], tot[p]);
        }
    }

    // diagonal correction: (cf*poly - cur) * e_d^2
    #pragma unroll
    for (int d = 0; d < D; d++) {
        u64 Addn = *(const u64*)&sAddn[d];
        u64 Bddp = *(const u64*)&sBdd[d];
        u64 ljp  = *(const u64*)&sLJ[d];
        u64 c1n  = *(const u64*)&sC1n[d];
        u64 c2p  = *(const u64*)&sC2[d];
        u64 c3p  = *(const u64*)&sC3[d];
        u64 cfp  = *(const u64*)&sCF[d];
        #pragma unroll
        for (int p = 0; p < NPAIR; p++) {
            u64 dd  = d2[p][d];
            u64 ed2 = mul2(e[p][d], e[p][d]);
            u64 curn = mul2(mul2(Addn, fma2(dd, NEG1, Bddp)),   // -A*(B-dd)*(lj-dd)
                            fma2(dd, NEG1, ljp));
            u64 poly = fma2(dd, fma2(c2p, dd, c1n), c3p);
            u64 corr = fma2(cfp, poly, curn);
            tot[p] = fma2(corr, ed2, tot[p]);
        }
    }

    const float s0 = sSig0;
    #pragma unroll
    for (int p = 0; p < NPAIR; p++) {
        u64 r = mul2(tot[p], e[p][0]);
        float lo, hi; unpack2(r, lo, hi);
        const int mbase = m0 + p * 64 + tx;
        out[n * NTOT + mbase]      = s0 * lo;
        out[n * NTOT + mbase + 32] = s0 * hi;
    }
}

extern "C" void kernel_launch(void* const* d_in, const int* in_sizes, int n_in,
                              void* d_out, int out_size) {
    const float* x1    = (const float*)d_in[0];
    const float* x2    = (const float*)d_in[1];
    const float* L     = (const float*)d_in[2];
    const float* sigma = (const float*)d_in[3];
    float* out = (float*)d_out;

    dim3 block(BX, BY);
    dim3 grid(NTOT / (BX * 2 * NPAIR), NTOT / BY);   // (8, 256)
    taylor_rbf_fused<<<grid, block>>>(x1, x2, L, sigma, out);
}

// round 3
// speedup vs baseline: 1.8475x; 1.1220x over previous
#include <cuda_runtime.h>

#define D 8
#define NTOT 1024
#define BX 32
#define BY 4
#define NPAIR 2   // 4 outputs per thread as 2 f32x2 pairs

typedef unsigned long long u64;

__device__ __forceinline__ u64 pack2(float lo, float hi) {
    u64 r; asm("mov.b64 %0, {%1,%2};" : "=l"(r) : "f"(lo), "f"(hi)); return r;
}
__device__ __forceinline__ void unpack2(u64 v, float& lo, float& hi) {
    asm("mov.b64 {%0,%1}, %2;" : "=f"(lo), "=f"(hi) : "l"(v));
}
__device__ __forceinline__ u64 fma2(u64 a, u64 b, u64 c) {
    u64 d; asm("fma.rn.f32x2 %0, %1, %2, %3;" : "=l"(d) : "l"(a), "l"(b), "l"(c)); return d;
}
__device__ __forceinline__ u64 mul2(u64 a, u64 b) {
    u64 d; asm("mul.rn.f32x2 %0, %1, %2;" : "=l"(d) : "l"(a), "l"(b)); return d;
}
__device__ __forceinline__ u64 add2(u64 a, u64 b) {
    u64 d; asm("add.rn.f32x2 %0, %1, %2;" : "=l"(d) : "l"(a), "l"(b)); return d;
}
__device__ __forceinline__ float ex2f(float x) {
    float r; asm("ex2.approx.ftz.f32 %0, %1;" : "=f"(r) : "f"(x)); return r;
}
__device__ __forceinline__ float frcp(float x) {
    float r; asm("rcp.approx.ftz.f32 %0, %1;" : "=f"(r) : "f"(x)); return r;
}
__device__ __forceinline__ u64 lo4(float4 v) { return pack2(v.x, v.y); }
__device__ __forceinline__ u64 hi4(float4 v) { return pack2(v.z, v.w); }

// All broadcast constants stored as DUPLICATED pairs: one float4 = two f32x2
// broadcast operands -> one LDS.128 feeds two FMA2s.
__global__ __launch_bounds__(BX * BY, 5)
void taylor_rbf_fused(const float* __restrict__ x1,
                      const float* __restrict__ x2,
                      const float* __restrict__ L,
                      const float* __restrict__ sigma,
                      float* __restrict__ out) {
    __shared__ float4 sAB4[32];   // [j*4+cp]: {AB_{2cp},AB,AB_{2cp+1},AB}  AB = cf_j*M
    __shared__ float4 sAn4[32];   // [j*4+cp]: -A = -cf_j*M^2
    __shared__ float4 sI4[32];    // [a*4+kp]: inv2[a][k] * (-0.5*log2 e)
    __shared__ float4 sD4[D][3];  // [d]: {-c1,-c1,c2,c2},{c3,c3,cf,cf},{-Add,-Add,Bdd,Bdd}
    __shared__ float2 sLJ[D];     // lij2_j (duplicated)
    __shared__ float  sSig0;
    __shared__ float2 sx2[D][NPAIR][BX];

    const int tx = threadIdx.x, ty = threadIdx.y;
    const int tid = ty * BX + tx;

    // ---- per-block constant precompute (spread across threads, approx rcp) ----
    if (tid < 64) {
        const int c = tid >> 3, j = tid & 7;
        float Ljc = L[j * D + c];
        float L0c = L[c];
        float i0c = frcp(L0c * L0c);
        float ijc = frcp(Ljc * Ljc);
        float M   = i0c + ijc;
        float l0j = L[j];
        float lij2 = l0j * l0j;
        float cf  = sigma[j] * frcp(lij2 * lij2);
        float AB  = cf * M;
        float An  = -AB * M;
        const int fo = j * 16 + (c >> 1) * 4 + (c & 1) * 2;
        float* pAB = (float*)sAB4; pAB[fo] = AB; pAB[fo + 1] = AB;
        float* pAn = (float*)sAn4; pAn[fo] = An; pAn[fo + 1] = An;
        // exp table, reusing (a,k) = (c,j)
        float Lak = L[c * D + j];
        float v = -0.72134752044448170368f * frcp(Lak * Lak);
        const int fi = c * 16 + (j >> 1) * 4 + (j & 1) * 2;
        float* pI = (float*)sI4; pI[fi] = v; pI[fi + 1] = v;
    } else if (tid < 72) {
        const int d = tid - 64;
        float l0 = L[d];
        float lij2 = l0 * l0;
        float Ldd = L[d * D + d];
        float idd = frcp(Ldd * Ldd);
        float i0d = frcp(lij2);
        float tl  = i0d + idd;
        float cf  = sigma[d] * frcp(lij2 * lij2);
        float Add = cf * tl * tl;
        float c1  = 5.0f * tl + lij2 * tl * tl;
        float c2  = tl * tl;
        float c3  = 2.0f + lij2 * tl;
        float bdd = frcp(tl);
        float* pD = (float*)&sD4[d][0];
        pD[0] = -c1;  pD[1] = -c1;  pD[2]  = c2;   pD[3]  = c2;
        pD[4] = c3;   pD[5] = c3;   pD[6]  = cf;   pD[7]  = cf;
        pD[8] = -Add; pD[9] = -Add; pD[10] = bdd;  pD[11] = bdd;
        sLJ[d] = make_float2(lij2, lij2);
    } else if (tid == 72) {
        sSig0 = sigma[0];
    }

    // ---- stage x2 tile: (m, m+32) packed into one float2 ----
    const int m0 = blockIdx.x * (BX * 2 * NPAIR);   // 128 m per block
    {
        const int r = tid;
        const int p = r >> 6;
        const int half = (r >> 5) & 1;
        const int t = r & 31;
        const float* src = x2 + (m0 + r) * D;
        #pragma unroll
        for (int k = 0; k < D; k++) {
            float* dst = (float*)&sx2[k][p][t] + half;
            *dst = src[k];
        }
    }
    __syncthreads();

    const int n = blockIdx.y * BY + ty;
    const u64 NEG1 = pack2(-1.0f, -1.0f);

    // diff^2, packed over the m-pair
    u64 d2[NPAIR][D];
    #pragma unroll
    for (int k = 0; k < D; k++) {
        float v = x1[n * D + k];
        u64 a1 = pack2(v, v);
        #pragma unroll
        for (int p = 0; p < NPAIR; p++) {
            u64 xp = *(const u64*)&sx2[k][p][tx];
            u64 dd = fma2(xp, NEG1, a1);
            d2[p][k] = mul2(dd, dd);
        }
    }

    // e[p][a] = exp(-0.5 * <d2, inv2[a,:]>) via pre-scaled rows + ex2
    u64 e[NPAIR][D];
    #pragma unroll
    for (int a = 0; a < D; a++) {
        float4 q0 = sI4[a * 4 + 0];
        float4 q1 = sI4[a * 4 + 1];
        float4 q2 = sI4[a * 4 + 2];
        float4 q3 = sI4[a * 4 + 3];
        u64 r0 = lo4(q0), r1 = hi4(q0), r2 = lo4(q1), r3 = hi4(q1);
        u64 r4 = lo4(q2), r5 = hi4(q2), r6 = lo4(q3), r7 = hi4(q3);
        #pragma unroll
        for (int p = 0; p < NPAIR; p++) {
            u64 s0 = mul2(d2[p][0], r0);
            u64 s1 = mul2(d2[p][1], r1);
            s0 = fma2(d2[p][2], r2, s0);
            s1 = fma2(d2[p][3], r3, s1);
            s0 = fma2(d2[p][4], r4, s0);
            s1 = fma2(d2[p][5], r5, s1);
            s0 = fma2(d2[p][6], r6, s0);
            s1 = fma2(d2[p][7], r7, s1);
            u64 s = add2(s0, s1);
            float lo, hi; unpack2(s, lo, hi);
            e[p][a] = pack2(ex2f(lo), ex2f(hi));
        }
    }

    u64 tot[NPAIR], totD[NPAIR];
    #pragma unroll
    for (int p = 0; p < NPAIR; p++) { tot[p] = pack2(0.f, 0.f); totD[p] = pack2(0.f, 0.f); }

    // merged double-sum + diagonal correction, one pass over j
    #pragma unroll
    for (int j = 0; j < D; j++) {
        u64 in0[NPAIR], in1[NPAIR];
        #pragma unroll
        for (int p = 0; p < NPAIR; p++) { in0[p] = pack2(0.f, 0.f); in1[p] = pack2(0.f, 0.f); }
        #pragma unroll
        for (int cp = 0; cp < 4; cp++) {
            float4 ab = sAB4[j * 4 + cp];
            float4 an = sAn4[j * 4 + cp];
            u64 AB0 = lo4(ab), AB1 = hi4(ab);
            u64 An0 = lo4(an), An1 = hi4(an);
            const int c0 = 2 * cp, c1 = 2 * cp + 1;
            #pragma unroll
            for (int p = 0; p < NPAIR; p++) {
                u64 t0 = fma2(An0, d2[p][c0], AB0);
                in0[p] = fma2(t0, e[p][c0], in0[p]);
                u64 t1 = fma2(An1, d2[p][c1], AB1);
                in1[p] = fma2(t1, e[p][c1], in1[p]);
            }
        }
        u64 ljp = *(const u64*)&sLJ[j];
        #pragma unroll
        for (int p = 0; p < NPAIR; p++) {
            u64 inn = add2(in0[p], in1[p]);
            u64 w = fma2(d2[p][j], NEG1, ljp);
            tot[p] = fma2(mul2(inn, w), e[p][j], tot[p]);
        }
        // diagonal term d == j
        float4 D0 = sD4[j][0], D1 = sD4[j][1], D2 = sD4[j][2];
        u64 c1n = lo4(D0), c2p = hi4(D0);
        u64 c3p = lo4(D1), cfp = hi4(D1);
        u64 Addn = lo4(D2), Bddp = hi4(D2);
        #pragma unroll
        for (int p = 0; p < NPAIR; p++) {
            u64 dd  = d2[p][j];
            u64 ed2 = mul2(e[p][j], e[p][j]);
            u64 curn = mul2(mul2(Addn, fma2(dd, NEG1, Bddp)),
                            fma2(dd, NEG1, ljp));
            u64 poly = fma2(dd, fma2(c2p, dd, c1n), c3p);
            totD[p] = fma2(fma2(cfp, poly, curn), ed2, totD[p]);
        }
    }

    const float s0 = sSig0;
    #pragma unroll
    for (int p = 0; p < NPAIR; p++) {
        u64 r = mul2(add2(tot[p], totD[p]), e[p][0]);
        float lo, hi; unpack2(r, lo, hi);
        const int mbase = m0 + p * 64 + tx;
        out[n * NTOT + mbase]      = s0 * lo;
        out[n * NTOT + mbase + 32] = s0 * hi;
    }
}

extern "C" void kernel_launch(void* const* d_in, const int* in_sizes, int n_in,
                              void* d_out, int out_size) {
    const float* x1    = (const float*)d_in[0];
    const float* x2    = (const float*)d_in[1];
    const float* L     = (const float*)d_in[2];
    const float* sigma = (const float*)d_in[3];
    float* out = (float*)d_out;

    dim3 block(BX, BY);
    dim3 grid(NTOT / (BX * 2 * NPAIR), NTOT / BY);   // (8, 256)
    taylor_rbf_fused<<<grid, block>>>(x1, x2, L, sigma, out);
}